// round 3
// baseline (speedup 1.0000x reference)
#include <cuda_runtime.h>
#include <cuda_bf16.h>
#include <cstdint>

// Problem constants
#define NN      8192
#define DD      512
#define SS      64
#define BI      128
#define BJ      128
#define DKC     16          // k-chunk
#define NSPLIT  8           // i-range splits (1024 rows each)
#define PADR    132         // smem row pad (floats): 528B, 16B-aligned, conflict-light

#define INV2SIG 0.0009765625f   // 1/(2*512)

// Scratch (device globals; no runtime allocation)
__device__ float  g_sq[NN];
__device__ float  g_Epart[NSPLIT * SS * NN];      // 16 MB partial E
__device__ double g_partial[2048];                // per-block loss partials

// ---------------------------------------------------------------------------
// Kernel 1: row squared norms. One warp per row.
// ---------------------------------------------------------------------------
__global__ void rownorm_kernel(const float* __restrict__ X) {
    int row  = blockIdx.x * 8 + (threadIdx.x >> 5);
    int lane = threadIdx.x & 31;
    const float4* xr = reinterpret_cast<const float4*>(X + (size_t)row * DD);
    float s = 0.f;
#pragma unroll
    for (int q = 0; q < 4; q++) {
        float4 v = xr[lane + q * 32];
        s += v.x * v.x + v.y * v.y + v.z * v.z + v.w * v.w;
    }
#pragma unroll
    for (int o = 16; o; o >>= 1) s += __shfl_xor_sync(0xFFFFFFFFu, s, o);
    if (lane == 0) g_sq[row] = s;
}

// ---------------------------------------------------------------------------
// Kernel 2: fused  K-tile GEMM + exp + E accumulation.
// grid = (64 J-tiles, 8 I-splits), 256 threads.
// Each block: for 8 i-tiles of 128 rows, compute K[128x128] = exp RBF of
// X[i-tile] x X[j-tile]^T, then E[s, jtile] += W[i-tile]^T K  (E in regs).
// ---------------------------------------------------------------------------
__global__ __launch_bounds__(256, 1)
void kpca_main_kernel(const float* __restrict__ X, const float* __restrict__ W) {
    __shared__ float As[DKC][PADR];
    __shared__ float Bs[DKC][PADR];
    __shared__ float Ksm[32][PADR];
    __shared__ float Wsm[32][SS];

    const int jt     = blockIdx.x;
    const int isplit = blockIdx.y;
    const int j0     = jt * BJ;
    const int t  = threadIdx.x;
    const int tx = t & 15;
    const int ty = t >> 4;

    // E accumulators: s = ty*4+v  (64 = 16*4),  j = j0 + tx*8+u (128 = 16*8)
    float Ereg[4][8];
#pragma unroll
    for (int v = 0; v < 4; v++)
#pragma unroll
        for (int u = 0; u < 8; u++) Ereg[v][u] = 0.f;

    float sqj[8];
#pragma unroll
    for (int u = 0; u < 8; u++) sqj[u] = g_sq[j0 + tx * 8 + u];

    // global-load mapping for A/B tiles: 128 rows x 16 cols, 2 float4 / thread
    const int lr  = t >> 2;            // 0..63
    const int lc4 = (t & 3) * 4;       // {0,4,8,12}

    for (int it = 0; it < 8; it++) {
        const int i0 = isplit * 1024 + it * BI;

        float acc[8][8];
#pragma unroll
        for (int u = 0; u < 8; u++)
#pragma unroll
            for (int v = 0; v < 8; v++) acc[u][v] = 0.f;

        for (int kc = 0; kc < DD; kc += DKC) {
            // prefetch to registers
            float4 av0 = *reinterpret_cast<const float4*>(&X[(size_t)(i0 + lr)      * DD + kc + lc4]);
            float4 av1 = *reinterpret_cast<const float4*>(&X[(size_t)(i0 + lr + 64) * DD + kc + lc4]);
            float4 bv0 = *reinterpret_cast<const float4*>(&X[(size_t)(j0 + lr)      * DD + kc + lc4]);
            float4 bv1 = *reinterpret_cast<const float4*>(&X[(size_t)(j0 + lr + 64) * DD + kc + lc4]);

            __syncthreads();   // previous k-chunk fully consumed
            As[lc4 + 0][lr] = av0.x;  As[lc4 + 1][lr] = av0.y;
            As[lc4 + 2][lr] = av0.z;  As[lc4 + 3][lr] = av0.w;
            As[lc4 + 0][lr + 64] = av1.x;  As[lc4 + 1][lr + 64] = av1.y;
            As[lc4 + 2][lr + 64] = av1.z;  As[lc4 + 3][lr + 64] = av1.w;
            Bs[lc4 + 0][lr] = bv0.x;  Bs[lc4 + 1][lr] = bv0.y;
            Bs[lc4 + 2][lr] = bv0.z;  Bs[lc4 + 3][lr] = bv0.w;
            Bs[lc4 + 0][lr + 64] = bv1.x;  Bs[lc4 + 1][lr + 64] = bv1.y;
            Bs[lc4 + 2][lr + 64] = bv1.z;  Bs[lc4 + 3][lr + 64] = bv1.w;
            __syncthreads();

#pragma unroll
            for (int k = 0; k < DKC; k++) {
                float4 a0 = *reinterpret_cast<const float4*>(&As[k][ty * 8]);
                float4 a1 = *reinterpret_cast<const float4*>(&As[k][ty * 8 + 4]);
                float4 b0 = *reinterpret_cast<const float4*>(&Bs[k][tx * 8]);
                float4 b1 = *reinterpret_cast<const float4*>(&Bs[k][tx * 8 + 4]);
                float a[8] = {a0.x, a0.y, a0.z, a0.w, a1.x, a1.y, a1.z, a1.w};
                float b[8] = {b0.x, b0.y, b0.z, b0.w, b1.x, b1.y, b1.z, b1.w};
#pragma unroll
                for (int u = 0; u < 8; u++)
#pragma unroll
                    for (int v = 0; v < 8; v++)
                        acc[u][v] = fmaf(a[u], b[v], acc[u][v]);
            }
        }

        // epilogue: d2 -> exp
        float sqi[8];
#pragma unroll
        for (int u = 0; u < 8; u++) sqi[u] = g_sq[i0 + ty * 8 + u];
#pragma unroll
        for (int u = 0; u < 8; u++)
#pragma unroll
            for (int v = 0; v < 8; v++)
                acc[u][v] = __expf((2.f * acc[u][v] - sqi[u] - sqj[v]) * INV2SIG);

        // E accumulation: 4 chunks of 32 K-rows
        const int wr  = t >> 3;          // 0..31
        const int wc  = (t & 7) * 8;     // 0..56
        for (int c = 0; c < 4; c++) {
            __syncthreads();    // previous chunk's Ksm/Wsm reads done
            if ((ty >> 2) == c) {
                const int tyl = ty & 3;
#pragma unroll
                for (int u = 0; u < 8; u++) {
                    *reinterpret_cast<float4*>(&Ksm[tyl * 8 + u][tx * 8]) =
                        make_float4(acc[u][0], acc[u][1], acc[u][2], acc[u][3]);
                    *reinterpret_cast<float4*>(&Ksm[tyl * 8 + u][tx * 8 + 4]) =
                        make_float4(acc[u][4], acc[u][5], acc[u][6], acc[u][7]);
                }
            }
            {
                const float* wp = &W[(size_t)(i0 + c * 32 + wr) * SS + wc];
                *reinterpret_cast<float4*>(&Wsm[wr][wc])     = *reinterpret_cast<const float4*>(wp);
                *reinterpret_cast<float4*>(&Wsm[wr][wc + 4]) = *reinterpret_cast<const float4*>(wp + 4);
            }
            __syncthreads();

#pragma unroll
            for (int ii = 0; ii < 32; ii++) {
                float4 w4 = *reinterpret_cast<const float4*>(&Wsm[ii][ty * 4]);
                float4 k0 = *reinterpret_cast<const float4*>(&Ksm[ii][tx * 8]);
                float4 k1 = *reinterpret_cast<const float4*>(&Ksm[ii][tx * 8 + 4]);
                float w[4] = {w4.x, w4.y, w4.z, w4.w};
                float kk[8] = {k0.x, k0.y, k0.z, k0.w, k1.x, k1.y, k1.z, k1.w};
#pragma unroll
                for (int v = 0; v < 4; v++)
#pragma unroll
                    for (int u = 0; u < 8; u++)
                        Ereg[v][u] = fmaf(w[v], kk[u], Ereg[v][u]);
            }
        }
    }

    // write partial E
#pragma unroll
    for (int v = 0; v < 4; v++) {
        float* dst = &g_Epart[(size_t)isplit * (SS * NN) + (size_t)(ty * 4 + v) * NN + j0 + tx * 8];
        *reinterpret_cast<float4*>(dst)     = make_float4(Ereg[v][0], Ereg[v][1], Ereg[v][2], Ereg[v][3]);
        *reinterpret_cast<float4*>(dst + 4) = make_float4(Ereg[v][4], Ereg[v][5], Ereg[v][6], Ereg[v][7]);
    }
}

// ---------------------------------------------------------------------------
// Kernel 3: combine E partials, per-element loss contribution, block reduce.
// grid 2048 x 256; one element per thread. Deterministic tree reduction.
// ---------------------------------------------------------------------------
__global__ void finalize_kernel(const float* __restrict__ W,
                                const float* __restrict__ invl) {
    const int tid = threadIdx.x;
    const int idx = blockIdx.x * 256 + tid;   // 0..524287
    const int s = idx >> 13;                  // /8192
    const int j = idx & (NN - 1);

    float E = 0.f;
#pragma unroll
    for (int p = 0; p < NSPLIT; p++) E += g_Epart[(size_t)p * (SS * NN) + idx];

    double Ed = (double)E;
    double contrib = 0.5 * Ed * ((double)W[(size_t)j * SS + s] - (double)invl[s] * Ed);

    __shared__ double sm[256];
    sm[tid] = contrib;
    __syncthreads();
#pragma unroll
    for (int o = 128; o; o >>= 1) {
        if (tid < o) sm[tid] += sm[tid + o];
        __syncthreads();
    }
    if (tid == 0) g_partial[blockIdx.x] = sm[0];
}

// ---------------------------------------------------------------------------
// Kernel 4: final deterministic reduction + nonlinearity.
// ---------------------------------------------------------------------------
__global__ void final_reduce_kernel(float* __restrict__ out) {
    __shared__ double sm[1024];
    const int tid = threadIdx.x;
    sm[tid] = g_partial[tid] + g_partial[tid + 1024];
    __syncthreads();
#pragma unroll
    for (int o = 512; o; o >>= 1) {
        if (tid < o) sm[tid] += sm[tid + o];
        __syncthreads();
    }
    if (tid == 0) {
        double L = sm[0];
        out[0] = (float)(L + 0.05 * L * L);
    }
}

// ---------------------------------------------------------------------------
extern "C" void kernel_launch(void* const* d_in, const int* in_sizes, int n_in,
                              void* d_out, int out_size) {
    const float* X    = (const float*)d_in[0];   // [8192, 512]
    const float* W    = (const float*)d_in[1];   // [8192, 64]
    const float* invl = (const float*)d_in[2];   // [64]
    float* out = (float*)d_out;

    rownorm_kernel<<<NN / 8, 256>>>(X);
    kpca_main_kernel<<<dim3(NN / BJ, NSPLIT), 256>>>(X, W);
    finalize_kernel<<<(SS * NN) / 256, 256>>>(W, invl);
    final_reduce_kernel<<<1, 1024>>>(out);
}